// round 14
// baseline (speedup 1.0000x reference)
#include <cuda_runtime.h>
#include <cuda_fp16.h>
#include <cstdint>
#include <cstddef>

#define NN   8192
#define FIN  256
#define FOUT 128
#define MT   64
#define JT   128
#define NT2  32
#define SPH  136
#define SBH  136
#define SA_BYTES 17408u
#define SB_BYTES 34816u

__device__ float  g_Wh[NN * FOUT];
__device__ __half g_WhT[FOUT * NN];
__device__ float  g_ss[NN], g_sd[NN];
__device__ float  g_us[NN], g_u5[NN];
__device__ float  g_vd[NN], g_v5[NN];
__device__ float  g_pnum[2 * NN * FOUT];
__device__ float  g_pden[2 * NN];

#define CPASYNC16(dst, src) \
    asm volatile("cp.async.cg.shared.global [%0], [%1], 16;" :: "r"(dst), "l"(src))
#define CPCOMMIT() asm volatile("cp.async.commit_group;" ::: "memory")
#define CPWAIT1()  asm volatile("cp.async.wait_group 1;" ::: "memory")
#define STS64(a, x, y) \
    asm volatile("st.shared.v2.b32 [%0], {%1,%2};" :: "r"(a), "r"(x), "r"(y) : "memory")
#define LDSM4(r0, r1, r2, r3, addr) \
    asm volatile("ldmatrix.sync.aligned.m8n8.x4.shared.b16 {%0,%1,%2,%3}, [%4];" \
                 : "=r"(r0), "=r"(r1), "=r"(r2), "=r"(r3) : "r"(addr))
#define MMA16(d, a0, a1, a2, a3, b0, b1) \
    asm volatile("mma.sync.aligned.m16n8k16.row.col.f32.f16.f16.f32 " \
                 "{%0,%1,%2,%3}, {%4,%5,%6,%7}, {%8,%9}, {%0,%1,%2,%3};\n" \
                 : "+f"(d[0]), "+f"(d[1]), "+f"(d[2]), "+f"(d[3]) \
                 : "r"(a0), "r"(a1), "r"(a2), "r"(a3), "r"(b0), "r"(b1))

__device__ __forceinline__ unsigned packh2(float a, float b) {
    __half2 h = __floats2half2_rn(a, b);
    return *reinterpret_cast<unsigned*>(&h);
}

// ---------------- Phase 1: Wh = h @ W^T (32 rows/CTA, occ 2) ----------------
__global__ void __launch_bounds__(256, 2) k_wh(const float* __restrict__ h,
                                               const float* __restrict__ W) {
    __shared__ float sH[32][36];
    __shared__ float sW[32][132];
    const int t = threadIdx.x, i0 = blockIdx.x * 32;
    const int rb = (t >> 5) * 4, cb = (t & 31) * 4;
    float acc[4][4];
#pragma unroll
    for (int r = 0; r < 4; r++)
#pragma unroll
        for (int c = 0; c < 4; c++) acc[r][c] = 0.f;
    for (int k0 = 0; k0 < FIN; k0 += 32) {
        __syncthreads();
        {
            int row = t >> 3, kc = (t & 7) * 4;
            float4 v = *reinterpret_cast<const float4*>(h + (size_t)(i0 + row) * FIN + k0 + kc);
            sH[kc][row] = v.x; sH[kc + 1][row] = v.y; sH[kc + 2][row] = v.z; sH[kc + 3][row] = v.w;
        }
#pragma unroll
        for (int it = 0; it < 4; it++) {
            int idx = t + 256 * it, f = idx >> 3, kc = (idx & 7) * 4;
            float4 v = *reinterpret_cast<const float4*>(W + (size_t)f * FIN + k0 + kc);
            sW[kc][f] = v.x; sW[kc + 1][f] = v.y; sW[kc + 2][f] = v.z; sW[kc + 3][f] = v.w;
        }
        __syncthreads();
#pragma unroll
        for (int k = 0; k < 32; k++) {
            float a[4], b[4];
            *reinterpret_cast<float4*>(a) = *reinterpret_cast<const float4*>(&sH[k][rb]);
            *reinterpret_cast<float4*>(b) = *reinterpret_cast<const float4*>(&sW[k][cb]);
#pragma unroll
            for (int r = 0; r < 4; r++)
#pragma unroll
                for (int c = 0; c < 4; c++) acc[r][c] = fmaf(a[r], b[c], acc[r][c]);
        }
    }
#pragma unroll
    for (int r = 0; r < 4; r++)
        *reinterpret_cast<float4*>(g_Wh + (size_t)(i0 + rb + r) * FOUT + cb) =
            make_float4(acc[r][0], acc[r][1], acc[r][2], acc[r][3]);
#pragma unroll
    for (int c = 0; c < 4; c++) {
        uint2 v;
        v.x = packh2(acc[0][c], acc[1][c]);
        v.y = packh2(acc[2][c], acc[3][c]);
        *reinterpret_cast<uint2*>(g_WhT + (size_t)(cb + c) * NN + i0 + rb) = v;
    }
}

// ---------------- Phase 2: raw scores ----------------
__global__ void __launch_bounds__(256) k_score(const float* __restrict__ a_vec) {
    int gw = (blockIdx.x * blockDim.x + threadIdx.x) >> 5, lane = threadIdx.x & 31;
    if (gw >= NN) return;
    float4 w  = reinterpret_cast<const float4*>(g_Wh + (size_t)gw * FOUT)[lane];
    float4 as = reinterpret_cast<const float4*>(a_vec)[lane];
    float4 ad = reinterpret_cast<const float4*>(a_vec + FOUT)[lane];
    float ss = w.x * as.x + w.y * as.y + w.z * as.z + w.w * as.w;
    float sd = w.x * ad.x + w.y * ad.y + w.z * ad.z + w.w * ad.w;
#pragma unroll
    for (int o = 16; o > 0; o >>= 1) {
        ss += __shfl_xor_sync(0xffffffffu, ss, o);
        sd += __shfl_xor_sync(0xffffffffu, sd, o);
    }
    if (lane == 0) { g_ss[gw] = ss; g_sd[gw] = sd; }
}

// ------- Phase 2b: prescaled exp factors (global max per block) -------
__global__ void __launch_bounds__(256) k_prep() {
    __shared__ float sm[8];
    __shared__ float sM;
    const int t = threadIdx.x;
    float m = -1e30f;
    for (int i = t; i < NN; i += 256) m = fmaxf(m, g_sd[i]);
#pragma unroll
    for (int o = 16; o > 0; o >>= 1) m = fmaxf(m, __shfl_xor_sync(0xffffffffu, m, o));
    if ((t & 31) == 0) sm[t >> 5] = m;
    __syncthreads();
    if (t == 0) {
        float r = sm[0];
#pragma unroll
        for (int i = 1; i < 8; i++) r = fmaxf(r, sm[i]);
        sM = r;
    }
    __syncthreads();
    const float M = sM;
    int i = blockIdx.x * 256 + t;
    float ss = g_ss[i], sd = g_sd[i];
    float x = ss + M;
    float LRm = x > 0.f ? x : 0.2f * x;
    g_us[i] = expf(ss - LRm);
    g_u5[i] = expf(fmaf(0.2f, ss, -LRm));
    g_vd[i] = expf(sd);
    g_v5[i] = expf(0.2f * sd);
}

// ------- Phase 3: fused numerator (split-J, 512 threads, occ 2) -------
extern __shared__ float dynsmem[];

__global__ void __launch_bounds__(512, 2) k_gat(const int* __restrict__ adj) {
    char* base = reinterpret_cast<char*>(dynsmem);
    const uint32_t sAu  = (uint32_t)__cvta_generic_to_shared(base);
    const uint32_t sBu0 = sAu + SA_BYTES;
    float* sDen = reinterpret_cast<float*>(base + SA_BYTES + 2 * SB_BYTES);

    const int t    = threadIdx.x;
    const int lane = t & 31;
    const int w    = t >> 5;               // 0..15
    const int i0    = (blockIdx.x >> 1) * MT;
    const int halfj = blockIdx.x & 1;
    const int jbase = halfj * (NN / 2);
    const int jl    = lane * 4;

    // P-gen rows: w + 16*it, it = 0..3
    float ssr[4], usr[4], u5r[4], den[4];
#pragma unroll
    for (int it = 0; it < 4; it++) {
        int gr = i0 + w + 16 * it;
        ssr[it] = g_ss[gr]; usr[it] = g_us[gr]; u5r[it] = g_u5[gr];
        den[it] = 0.f;
    }

    // MMA warp grid: 4 row-blocks (16 rows) x 4 col-blocks (32 cols)
    const int mrow = (w & 3) * 16;
    const int ncol = (w >> 2) * 32;
    const int qr   = lane >> 2;
    const int qc   = lane & 3;

    const int lr8 = lane & 7;
    const int lhb = (lane >> 3) & 1;
    const int lcb = lane >> 4;
    const uint32_t aAdr = sAu + (uint32_t)((mrow + lr8 + 8 * lhb) * SPH * 2)
                        + (uint32_t)(lcb * 16);
    uint32_t bAdr[2];
#pragma unroll
    for (int g = 0; g < 2; g++) {
        int r = ncol + g * 16 + lr8 + 8 * lhb;
        bAdr[g] = (uint32_t)(r * SBH * 2) + (uint32_t)(lcb * 16);
    }

    float acc[4][4];
#pragma unroll
    for (int nb = 0; nb < 4; nb++)
#pragma unroll
        for (int c = 0; c < 4; c++) acc[nb][c] = 0.f;

    // ---- prologue: B(0) cp.async + tile-0 regs ----
#pragma unroll
    for (int i = 0; i < 4; i++) {
        int g = t + 512 * i, n = g >> 4, c = g & 15;
        CPASYNC16(sBu0 + (uint32_t)(n * SBH * 2 + c * 16),
                  g_WhT + (size_t)n * NN + jbase + c * 8);
    }
    CPCOMMIT();
    float4 sdC = *reinterpret_cast<const float4*>(g_sd + jbase + jl);
    float4 vdC = *reinterpret_cast<const float4*>(g_vd + jbase + jl);
    float4 v5C = *reinterpret_cast<const float4*>(g_v5 + jbase + jl);
    unsigned mcur = 0;
#pragma unroll
    for (int it = 0; it < 4; it++) {
        int4 am = *reinterpret_cast<const int4*>(adj + (size_t)(i0 + w + 16 * it) * NN + jbase + jl);
        unsigned b = (am.x > 0 ? 1u : 0u) | (am.y > 0 ? 2u : 0u)
                   | (am.z > 0 ? 4u : 0u) | (am.w > 0 ? 8u : 0u);
        mcur |= b << (4 * it);
    }

    for (int jt = 0; jt < NT2; jt++) {
        const int s = jt & 1;

        // ---- P-gen(jt): rows w+16it, cols jl..jl+3 -> sA (fp16) ----
#pragma unroll
        for (int it = 0; it < 4; it++) {
            int r = w + 16 * it;
            unsigned mk = mcur >> (4 * it);
            float p0 = (ssr[it] + sdC.x) > 0.f ? usr[it] * vdC.x : u5r[it] * v5C.x;
            float p1 = (ssr[it] + sdC.y) > 0.f ? usr[it] * vdC.y : u5r[it] * v5C.y;
            float p2 = (ssr[it] + sdC.z) > 0.f ? usr[it] * vdC.z : u5r[it] * v5C.z;
            float p3 = (ssr[it] + sdC.w) > 0.f ? usr[it] * vdC.w : u5r[it] * v5C.w;
            p0 = (mk & 1u) ? p0 : 0.f;
            p1 = (mk & 2u) ? p1 : 0.f;
            p2 = (mk & 4u) ? p2 : 0.f;
            p3 = (mk & 8u) ? p3 : 0.f;
            den[it] += (p0 + p1) + (p2 + p3);
            STS64(sAu + (uint32_t)(r * SPH + jl) * 2u, packh2(p0, p1), packh2(p2, p3));
        }

        // ---- prefetch regs(jt+1) ----
        if (jt + 1 < NT2) {
            const int j0n = jbase + (jt + 1) * JT;
            sdC = *reinterpret_cast<const float4*>(g_sd + j0n + jl);
            vdC = *reinterpret_cast<const float4*>(g_vd + j0n + jl);
            v5C = *reinterpret_cast<const float4*>(g_v5 + j0n + jl);
            unsigned mn = 0;
#pragma unroll
            for (int it = 0; it < 4; it++) {
                int4 am = *reinterpret_cast<const int4*>(
                    adj + (size_t)(i0 + w + 16 * it) * NN + j0n + jl);
                unsigned b = (am.x > 0 ? 1u : 0u) | (am.y > 0 ? 2u : 0u)
                           | (am.z > 0 ? 4u : 0u) | (am.w > 0 ? 8u : 0u);
                mn |= b << (4 * it);
            }
            mcur = mn;
        }

        // ---- cp.async B(jt+1) -> other buffer ----
        if (jt + 1 < NT2) {
            const __half* bsrc = g_WhT + jbase + (jt + 1) * JT;
            const uint32_t d = sBu0 + (uint32_t)(s ^ 1) * SB_BYTES;
#pragma unroll
            for (int i = 0; i < 4; i++) {
                int g = t + 512 * i, n = g >> 4, c = g & 15;
                CPASYNC16(d + (uint32_t)(n * SBH * 2 + c * 16),
                          bsrc + (size_t)n * NN + c * 8);
            }
        }
        CPCOMMIT();
        CPWAIT1();         // B(jt) resident
        __syncthreads();   // sA(jt) published

        // ---- MMA(jt): 1 A-ldmatrix + 2 B-ldmatrix + 4 MMA per k-step ----
        const uint32_t bS = sBu0 + (uint32_t)s * SB_BYTES;
#pragma unroll
        for (int ks = 0; ks < 8; ks++) {
            const uint32_t ko = (uint32_t)(ks * 32);
            unsigned a[4], b[2][4];
            LDSM4(a[0], a[1], a[2], a[3], aAdr + ko);
#pragma unroll
            for (int g = 0; g < 2; g++)
                LDSM4(b[g][0], b[g][1], b[g][2], b[g][3], bS + bAdr[g] + ko);
#pragma unroll
            for (int g = 0; g < 2; g++) {
                MMA16(acc[2 * g],     a[0], a[1], a[2], a[3], b[g][0], b[g][2]);
                MMA16(acc[2 * g + 1], a[0], a[1], a[2], a[3], b[g][1], b[g][3]);
            }
        }
        __syncthreads();   // sA / sB[s] free
    }

    // ---- partial denominators ----
#pragma unroll
    for (int it = 0; it < 4; it++) {
        float d = den[it];
#pragma unroll
        for (int o = 16; o > 0; o >>= 1) d += __shfl_xor_sync(0xffffffffu, d, o);
        if (lane == 0) sDen[w + 16 * it] = d;
    }
    __syncthreads();

    if (t < MT) g_pden[(size_t)halfj * NN + i0 + t] = sDen[t];
    float* pn = g_pnum + (size_t)halfj * NN * FOUT;
    {
        const int rbase = mrow + qr;
        const int r0 = i0 + rbase;
#pragma unroll
        for (int nb = 0; nb < 4; nb++) {
            int col = ncol + nb * 8 + qc * 2;
            *reinterpret_cast<float2*>(pn + (size_t)r0 * FOUT + col) =
                make_float2(acc[nb][0], acc[nb][1]);
            *reinterpret_cast<float2*>(pn + (size_t)(r0 + 8) * FOUT + col) =
                make_float2(acc[nb][2], acc[nb][3]);
        }
    }
}

// ---------------- Phase 4: combine split-J partials ----------------
__global__ void __launch_bounds__(256) k_combine(float* __restrict__ out) {
    int idx = blockIdx.x * 256 + threadIdx.x;
#pragma unroll
    for (int it = 0; it < 8; it++, idx += 32768) {
        int i = idx >> 5;
        float4 a = reinterpret_cast<const float4*>(g_pnum)[idx];
        float4 b = reinterpret_cast<const float4*>(g_pnum + (size_t)NN * FOUT)[idx];
        float rd = 1.f / (g_pden[i] + g_pden[NN + i]);
        reinterpret_cast<float4*>(out)[idx] = make_float4(
            (a.x + b.x) * rd, (a.y + b.y) * rd, (a.z + b.z) * rd, (a.w + b.w) * rd);
    }
}

// ---------------------------------------------------------------
extern "C" void kernel_launch(void* const* d_in, const int* in_sizes, int n_in,
                              void* d_out, int out_size) {
    const float* h   = (const float*)d_in[0];
    const int*   adj = (const int*)d_in[1];
    const float* W   = (const float*)d_in[2];
    const float* a   = (const float*)d_in[3];
    float*       out = (float*)d_out;
    (void)in_sizes; (void)n_in; (void)out_size;

    const int smem_bytes = (int)(SA_BYTES + 2 * SB_BYTES) + 256;
    static int inited = 0;
    if (!inited) {
        cudaFuncSetAttribute(k_gat, cudaFuncAttributeMaxDynamicSharedMemorySize, smem_bytes);
        inited = 1;
    }
    k_wh<<<NN / 32, 256>>>(h, W);
    k_score<<<NN / 8, 256>>>(a);
    k_prep<<<NN / 256, 256>>>();
    k_gat<<<2 * (NN / MT), 512, smem_bytes>>>(adj);
    k_combine<<<128, 256>>>(out);
}

// round 15
// speedup vs baseline: 1.0680x; 1.0680x over previous
#include <cuda_runtime.h>
#include <cuda_fp16.h>
#include <cstdint>
#include <cstddef>

#define NN   8192
#define FIN  256
#define FOUT 128
#define MT   64
#define JT   128
#define NT2  32
#define SPH  136
#define SBH  136
#define SA_BYTES 17408u
#define SB_BYTES 34816u

__device__ float  g_Wh[NN * FOUT];
__device__ __half g_WhT[FOUT * NN];
__device__ float  g_ss[NN], g_sd[NN];
__device__ float  g_us[NN], g_u5[NN];
__device__ float  g_vd[NN], g_v5[NN];
__device__ float  g_pnum[2 * NN * FOUT];
__device__ float  g_pden[2 * NN];

#define CPASYNC16(dst, src) \
    asm volatile("cp.async.cg.shared.global [%0], [%1], 16;" :: "r"(dst), "l"(src))
#define CPCOMMIT() asm volatile("cp.async.commit_group;" ::: "memory")
#define CPWAIT1()  asm volatile("cp.async.wait_group 1;" ::: "memory")
#define STS64(a, x, y) \
    asm volatile("st.shared.v2.b32 [%0], {%1,%2};" :: "r"(a), "r"(x), "r"(y) : "memory")
#define LDSM4(r0, r1, r2, r3, addr) \
    asm volatile("ldmatrix.sync.aligned.m8n8.x4.shared.b16 {%0,%1,%2,%3}, [%4];" \
                 : "=r"(r0), "=r"(r1), "=r"(r2), "=r"(r3) : "r"(addr))
#define MMA16(d, a0, a1, a2, a3, b0, b1) \
    asm volatile("mma.sync.aligned.m16n8k16.row.col.f32.f16.f16.f32 " \
                 "{%0,%1,%2,%3}, {%4,%5,%6,%7}, {%8,%9}, {%0,%1,%2,%3};\n" \
                 : "+f"(d[0]), "+f"(d[1]), "+f"(d[2]), "+f"(d[3]) \
                 : "r"(a0), "r"(a1), "r"(a2), "r"(a3), "r"(b0), "r"(b1))

__device__ __forceinline__ unsigned packh2(float a, float b) {
    __half2 h = __floats2half2_rn(a, b);
    return *reinterpret_cast<unsigned*>(&h);
}
__device__ __forceinline__ int4 ldcs4(const int* p) {
    int4 v;
    asm volatile("ld.global.cs.v4.b32 {%0,%1,%2,%3}, [%4];"
                 : "=r"(v.x), "=r"(v.y), "=r"(v.z), "=r"(v.w) : "l"(p));
    return v;
}

// ------- Phase 1: Wh = h @ W^T (+ fp16 Wh^T, + raw scores in epilogue) -------
__global__ void __launch_bounds__(256, 2) k_wh(const float* __restrict__ h,
                                               const float* __restrict__ W,
                                               const float* __restrict__ a_vec) {
    __shared__ float sH[32][36];
    __shared__ float sW[32][132];
    const int t = threadIdx.x, i0 = blockIdx.x * 32;
    const int lane = t & 31;
    const int rb = (t >> 5) * 4, cb = (t & 31) * 4;
    float acc[4][4];
#pragma unroll
    for (int r = 0; r < 4; r++)
#pragma unroll
        for (int c = 0; c < 4; c++) acc[r][c] = 0.f;
    for (int k0 = 0; k0 < FIN; k0 += 32) {
        __syncthreads();
        {
            int row = t >> 3, kc = (t & 7) * 4;
            float4 v = *reinterpret_cast<const float4*>(h + (size_t)(i0 + row) * FIN + k0 + kc);
            sH[kc][row] = v.x; sH[kc + 1][row] = v.y; sH[kc + 2][row] = v.z; sH[kc + 3][row] = v.w;
        }
#pragma unroll
        for (int it = 0; it < 4; it++) {
            int idx = t + 256 * it, f = idx >> 3, kc = (idx & 7) * 4;
            float4 v = *reinterpret_cast<const float4*>(W + (size_t)f * FIN + k0 + kc);
            sW[kc][f] = v.x; sW[kc + 1][f] = v.y; sW[kc + 2][f] = v.z; sW[kc + 3][f] = v.w;
        }
        __syncthreads();
#pragma unroll
        for (int k = 0; k < 32; k++) {
            float a[4], b[4];
            *reinterpret_cast<float4*>(a) = *reinterpret_cast<const float4*>(&sH[k][rb]);
            *reinterpret_cast<float4*>(b) = *reinterpret_cast<const float4*>(&sW[k][cb]);
#pragma unroll
            for (int r = 0; r < 4; r++)
#pragma unroll
                for (int c = 0; c < 4; c++) acc[r][c] = fmaf(a[r], b[c], acc[r][c]);
        }
    }
#pragma unroll
    for (int r = 0; r < 4; r++)
        *reinterpret_cast<float4*>(g_Wh + (size_t)(i0 + rb + r) * FOUT + cb) =
            make_float4(acc[r][0], acc[r][1], acc[r][2], acc[r][3]);
#pragma unroll
    for (int c = 0; c < 4; c++) {
        uint2 v;
        v.x = packh2(acc[0][c], acc[1][c]);
        v.y = packh2(acc[2][c], acc[3][c]);
        *reinterpret_cast<uint2*>(g_WhT + (size_t)(cb + c) * NN + i0 + rb) = v;
    }
    // ---- epilogue: raw scores for this warp's 4 rows ----
    {
        float4 asv = *reinterpret_cast<const float4*>(a_vec + cb);
        float4 adv = *reinterpret_cast<const float4*>(a_vec + FOUT + cb);
#pragma unroll
        for (int r = 0; r < 4; r++) {
            float ss = acc[r][0] * asv.x + acc[r][1] * asv.y
                     + acc[r][2] * asv.z + acc[r][3] * asv.w;
            float sd = acc[r][0] * adv.x + acc[r][1] * adv.y
                     + acc[r][2] * adv.z + acc[r][3] * adv.w;
#pragma unroll
            for (int o = 16; o > 0; o >>= 1) {
                ss += __shfl_xor_sync(0xffffffffu, ss, o);
                sd += __shfl_xor_sync(0xffffffffu, sd, o);
            }
            if (lane == 0) {
                g_ss[i0 + rb + r] = ss;
                g_sd[i0 + rb + r] = sd;
            }
        }
    }
}

// ------- Phase 2: prescaled exp factors (global max per block) -------
__global__ void __launch_bounds__(256) k_prep() {
    __shared__ float sm[8];
    __shared__ float sM;
    const int t = threadIdx.x;
    float m = -1e30f;
    for (int i = t; i < NN; i += 256) m = fmaxf(m, g_sd[i]);
#pragma unroll
    for (int o = 16; o > 0; o >>= 1) m = fmaxf(m, __shfl_xor_sync(0xffffffffu, m, o));
    if ((t & 31) == 0) sm[t >> 5] = m;
    __syncthreads();
    if (t == 0) {
        float r = sm[0];
#pragma unroll
        for (int i = 1; i < 8; i++) r = fmaxf(r, sm[i]);
        sM = r;
    }
    __syncthreads();
    const float M = sM;
    int i = blockIdx.x * 256 + t;
    float ss = g_ss[i], sd = g_sd[i];
    float x = ss + M;
    float LRm = x > 0.f ? x : 0.2f * x;
    g_us[i] = expf(ss - LRm);
    g_u5[i] = expf(fmaf(0.2f, ss, -LRm));
    g_vd[i] = expf(sd);
    g_v5[i] = expf(0.2f * sd);
}

// ------- Phase 3: fused numerator (split-J, occ 2, ldmatrix operands) -------
extern __shared__ float dynsmem[];

__global__ void __launch_bounds__(256, 2) k_gat(const int* __restrict__ adj) {
    char* base = reinterpret_cast<char*>(dynsmem);
    const uint32_t sAu  = (uint32_t)__cvta_generic_to_shared(base);
    const uint32_t sBu0 = sAu + SA_BYTES;
    float* sDen = reinterpret_cast<float*>(base + SA_BYTES + 2 * SB_BYTES);

    const int t    = threadIdx.x;
    const int lane = t & 31;
    const int w    = t >> 5;
    const int i0    = (blockIdx.x >> 1) * MT;
    const int halfj = blockIdx.x & 1;
    const int jbase = halfj * (NN / 2);
    const int jl    = lane * 4;

    float ssr[8], usr[8], u5r[8], den[8];
#pragma unroll
    for (int it = 0; it < 8; it++) {
        int gr = i0 + w + 8 * it;
        ssr[it] = g_ss[gr]; usr[it] = g_us[gr]; u5r[it] = g_u5[gr];
        den[it] = 0.f;
    }

    const int mrow = (w & 1) * 32;
    const int ncol = (w >> 1) * 32;
    const int qr   = lane >> 2;
    const int qc   = lane & 3;

    const int lr8 = lane & 7;
    const int lhb = (lane >> 3) & 1;
    const int lcb = lane >> 4;
    uint32_t aAdr[2], bAdr[2];
#pragma unroll
    for (int mb = 0; mb < 2; mb++) {
        int r = mrow + mb * 16 + lr8 + 8 * lhb;
        aAdr[mb] = sAu + (uint32_t)(r * SPH * 2) + (uint32_t)(lcb * 16);
    }
#pragma unroll
    for (int g = 0; g < 2; g++) {
        int r = ncol + g * 16 + lr8 + 8 * lhb;
        bAdr[g] = (uint32_t)(r * SBH * 2) + (uint32_t)(lcb * 16);
    }

    float acc[2][4][4];
#pragma unroll
    for (int mb = 0; mb < 2; mb++)
#pragma unroll
        for (int nb = 0; nb < 4; nb++)
#pragma unroll
            for (int c = 0; c < 4; c++) acc[mb][nb][c] = 0.f;

    // ---- prologue: B(0) cp.async + tile-0 regs ----
#pragma unroll
    for (int i = 0; i < 8; i++) {
        int g = t + 256 * i, n = g >> 4, c = g & 15;
        CPASYNC16(sBu0 + (uint32_t)(n * SBH * 2 + c * 16),
                  g_WhT + (size_t)n * NN + jbase + c * 8);
    }
    CPCOMMIT();
    float4 sdC = *reinterpret_cast<const float4*>(g_sd + jbase + jl);
    float4 vdC = *reinterpret_cast<const float4*>(g_vd + jbase + jl);
    float4 v5C = *reinterpret_cast<const float4*>(g_v5 + jbase + jl);
    unsigned mcur = 0;
#pragma unroll
    for (int it = 0; it < 8; it++) {
        int4 am = ldcs4(adj + (size_t)(i0 + w + 8 * it) * NN + jbase + jl);
        unsigned b = (am.x > 0 ? 1u : 0u) | (am.y > 0 ? 2u : 0u)
                   | (am.z > 0 ? 4u : 0u) | (am.w > 0 ? 8u : 0u);
        mcur |= b << (4 * it);
    }

    for (int jt = 0; jt < NT2; jt++) {
        const int s = jt & 1;

        // ---- cp.async B(jt+1) first (sB[s^1] free since MMA(jt-1) drained) ----
        if (jt + 1 < NT2) {
            const __half* bsrc = g_WhT + jbase + (jt + 1) * JT;
            const uint32_t d = sBu0 + (uint32_t)(s ^ 1) * SB_BYTES;
#pragma unroll
            for (int i = 0; i < 8; i++) {
                int g = t + 256 * i, n = g >> 4, c = g & 15;
                CPASYNC16(d + (uint32_t)(n * SBH * 2 + c * 16),
                          bsrc + (size_t)n * NN + c * 8);
            }
        }
        CPCOMMIT();

        // ---- P-gen(jt) -> sA (fp16) ----
#pragma unroll
        for (int it = 0; it < 8; it++) {
            int r = w + 8 * it;
            unsigned mk = mcur >> (4 * it);
            float p0 = (ssr[it] + sdC.x) > 0.f ? usr[it] * vdC.x : u5r[it] * v5C.x;
            float p1 = (ssr[it] + sdC.y) > 0.f ? usr[it] * vdC.y : u5r[it] * v5C.y;
            float p2 = (ssr[it] + sdC.z) > 0.f ? usr[it] * vdC.z : u5r[it] * v5C.z;
            float p3 = (ssr[it] + sdC.w) > 0.f ? usr[it] * vdC.w : u5r[it] * v5C.w;
            p0 = (mk & 1u) ? p0 : 0.f;
            p1 = (mk & 2u) ? p1 : 0.f;
            p2 = (mk & 4u) ? p2 : 0.f;
            p3 = (mk & 8u) ? p3 : 0.f;
            den[it] += (p0 + p1) + (p2 + p3);
            STS64(sAu + (uint32_t)(r * SPH + jl) * 2u, packh2(p0, p1), packh2(p2, p3));
        }

        // ---- prefetch regs(jt+1) ----
        if (jt + 1 < NT2) {
            const int j0n = jbase + (jt + 1) * JT;
            sdC = *reinterpret_cast<const float4*>(g_sd + j0n + jl);
            vdC = *reinterpret_cast<const float4*>(g_vd + j0n + jl);
            v5C = *reinterpret_cast<const float4*>(g_v5 + j0n + jl);
            unsigned mn = 0;
#pragma unroll
            for (int it = 0; it < 8; it++) {
                int4 am = ldcs4(adj + (size_t)(i0 + w + 8 * it) * NN + j0n + jl);
                unsigned b = (am.x > 0 ? 1u : 0u) | (am.y > 0 ? 2u : 0u)
                           | (am.z > 0 ? 4u : 0u) | (am.w > 0 ? 8u : 0u);
                mn |= b << (4 * it);
            }
            mcur = mn;
        }

        CPWAIT1();         // B(jt) resident
        __syncthreads();   // sA(jt) published

        // ---- MMA(jt): ldmatrix operands (4 per k-step) ----
        const uint32_t bS = sBu0 + (uint32_t)s * SB_BYTES;
#pragma unroll
        for (int ks = 0; ks < 8; ks++) {
            const uint32_t ko = (uint32_t)(ks * 32);
            unsigned a[2][4], b[2][4];
#pragma unroll
            for (int mb = 0; mb < 2; mb++)
                LDSM4(a[mb][0], a[mb][1], a[mb][2], a[mb][3], aAdr[mb] + ko);
#pragma unroll
            for (int g = 0; g < 2; g++)
                LDSM4(b[g][0], b[g][1], b[g][2], b[g][3], bS + bAdr[g] + ko);
#pragma unroll
            for (int mb = 0; mb < 2; mb++)
#pragma unroll
                for (int g = 0; g < 2; g++) {
                    MMA16(acc[mb][2 * g],     a[mb][0], a[mb][1], a[mb][2], a[mb][3],
                          b[g][0], b[g][2]);
                    MMA16(acc[mb][2 * g + 1], a[mb][0], a[mb][1], a[mb][2], a[mb][3],
                          b[g][1], b[g][3]);
                }
        }
        __syncthreads();   // sA / sB[s] free
    }

    // ---- partial denominators ----
#pragma unroll
    for (int it = 0; it < 8; it++) {
        float d = den[it];
#pragma unroll
        for (int o = 16; o > 0; o >>= 1) d += __shfl_xor_sync(0xffffffffu, d, o);
        if (lane == 0) sDen[w + 8 * it] = d;
    }
    __syncthreads();

    if (t < MT) g_pden[(size_t)halfj * NN + i0 + t] = sDen[t];
    float* pn = g_pnum + (size_t)halfj * NN * FOUT;
#pragma unroll
    for (int mb = 0; mb < 2; mb++) {
        const int rbase = mrow + mb * 16 + qr;
        const int r0 = i0 + rbase;
#pragma unroll
        for (int nb = 0; nb < 4; nb++) {
            int col = ncol + nb * 8 + qc * 2;
            *reinterpret_cast<float2*>(pn + (size_t)r0 * FOUT + col) =
                make_float2(acc[mb][nb][0], acc[mb][nb][1]);
            *reinterpret_cast<float2*>(pn + (size_t)(r0 + 8) * FOUT + col) =
                make_float2(acc[mb][nb][2], acc[mb][nb][3]);
        }
    }
}

// ---------------- Phase 4: combine split-J partials ----------------
__global__ void __launch_bounds__(256) k_combine(float* __restrict__ out) {
    int idx = blockIdx.x * 256 + threadIdx.x;
#pragma unroll
    for (int it = 0; it < 8; it++, idx += 32768) {
        int i = idx >> 5;
        float4 a = reinterpret_cast<const float4*>(g_pnum)[idx];
        float4 b = reinterpret_cast<const float4*>(g_pnum + (size_t)NN * FOUT)[idx];
        float rd = 1.f / (g_pden[i] + g_pden[NN + i]);
        reinterpret_cast<float4*>(out)[idx] = make_float4(
            (a.x + b.x) * rd, (a.y + b.y) * rd, (a.z + b.z) * rd, (a.w + b.w) * rd);
    }
}

// ---------------------------------------------------------------
extern "C" void kernel_launch(void* const* d_in, const int* in_sizes, int n_in,
                              void* d_out, int out_size) {
    const float* h   = (const float*)d_in[0];
    const int*   adj = (const int*)d_in[1];
    const float* W   = (const float*)d_in[2];
    const float* a   = (const float*)d_in[3];
    float*       out = (float*)d_out;
    (void)in_sizes; (void)n_in; (void)out_size;

    const int smem_bytes = (int)(SA_BYTES + 2 * SB_BYTES) + 256;
    static int inited = 0;
    if (!inited) {
        cudaFuncSetAttribute(k_gat, cudaFuncAttributeMaxDynamicSharedMemorySize, smem_bytes);
        inited = 1;
    }
    k_wh<<<NN / 32, 256>>>(h, W, a);
    k_prep<<<NN / 256, 256>>>();
    k_gat<<<2 * (NN / MT), 256, smem_bytes>>>(adj);
    k_combine<<<128, 256>>>(out);
}

// round 16
// speedup vs baseline: 1.1231x; 1.0515x over previous
#include <cuda_runtime.h>
#include <cuda_fp16.h>
#include <cstdint>
#include <cstddef>

#define NN   8192
#define FIN  256
#define FOUT 128
#define MT   64
#define JT   128
#define NT2  32
#define SPH  136
#define SBH  136
#define SA_BYTES 17408u
#define SB_BYTES 34816u

__device__ float  g_Wh[NN * FOUT];
__device__ __half g_WhT[FOUT * NN];
__device__ float  g_ss[NN], g_sd[NN];
__device__ float  g_us[NN], g_u5[NN];
__device__ float  g_vd[NN], g_v5[NN];
__device__ float  g_pnum[2 * NN * FOUT];
__device__ float  g_pden[2 * NN];
__device__ int    g_cnt[NN / MT];

#define CPASYNC16(dst, src) \
    asm volatile("cp.async.cg.shared.global [%0], [%1], 16;" :: "r"(dst), "l"(src))
#define CPCOMMIT() asm volatile("cp.async.commit_group;" ::: "memory")
#define CPWAIT1()  asm volatile("cp.async.wait_group 1;" ::: "memory")
#define STS64(a, x, y) \
    asm volatile("st.shared.v2.b32 [%0], {%1,%2};" :: "r"(a), "r"(x), "r"(y) : "memory")
#define LDSM4(r0, r1, r2, r3, addr) \
    asm volatile("ldmatrix.sync.aligned.m8n8.x4.shared.b16 {%0,%1,%2,%3}, [%4];" \
                 : "=r"(r0), "=r"(r1), "=r"(r2), "=r"(r3) : "r"(addr))
#define MMA16(d, a0, a1, a2, a3, b0, b1) \
    asm volatile("mma.sync.aligned.m16n8k16.row.col.f32.f16.f16.f32 " \
                 "{%0,%1,%2,%3}, {%4,%5,%6,%7}, {%8,%9}, {%0,%1,%2,%3};\n" \
                 : "+f"(d[0]), "+f"(d[1]), "+f"(d[2]), "+f"(d[3]) \
                 : "r"(a0), "r"(a1), "r"(a2), "r"(a3), "r"(b0), "r"(b1))

__device__ __forceinline__ unsigned packh2(float a, float b) {
    __half2 h = __floats2half2_rn(a, b);
    return *reinterpret_cast<unsigned*>(&h);
}

// ------- Phase 1: Wh = h @ W^T (+ fp16 Wh^T, + raw scores in epilogue) -------
__global__ void __launch_bounds__(256, 2) k_wh(const float* __restrict__ h,
                                               const float* __restrict__ W,
                                               const float* __restrict__ a_vec) {
    __shared__ float sH[32][36];
    __shared__ float sW[32][132];
    const int t = threadIdx.x, i0 = blockIdx.x * 32;
    const int lane = t & 31;
    const int rb = (t >> 5) * 4, cb = (t & 31) * 4;
    float acc[4][4];
#pragma unroll
    for (int r = 0; r < 4; r++)
#pragma unroll
        for (int c = 0; c < 4; c++) acc[r][c] = 0.f;
    for (int k0 = 0; k0 < FIN; k0 += 32) {
        __syncthreads();
        {
            int row = t >> 3, kc = (t & 7) * 4;
            float4 v = *reinterpret_cast<const float4*>(h + (size_t)(i0 + row) * FIN + k0 + kc);
            sH[kc][row] = v.x; sH[kc + 1][row] = v.y; sH[kc + 2][row] = v.z; sH[kc + 3][row] = v.w;
        }
#pragma unroll
        for (int it = 0; it < 4; it++) {
            int idx = t + 256 * it, f = idx >> 3, kc = (idx & 7) * 4;
            float4 v = *reinterpret_cast<const float4*>(W + (size_t)f * FIN + k0 + kc);
            sW[kc][f] = v.x; sW[kc + 1][f] = v.y; sW[kc + 2][f] = v.z; sW[kc + 3][f] = v.w;
        }
        __syncthreads();
#pragma unroll
        for (int k = 0; k < 32; k++) {
            float a[4], b[4];
            *reinterpret_cast<float4*>(a) = *reinterpret_cast<const float4*>(&sH[k][rb]);
            *reinterpret_cast<float4*>(b) = *reinterpret_cast<const float4*>(&sW[k][cb]);
#pragma unroll
            for (int r = 0; r < 4; r++)
#pragma unroll
                for (int c = 0; c < 4; c++) acc[r][c] = fmaf(a[r], b[c], acc[r][c]);
        }
    }
#pragma unroll
    for (int r = 0; r < 4; r++)
        *reinterpret_cast<float4*>(g_Wh + (size_t)(i0 + rb + r) * FOUT + cb) =
            make_float4(acc[r][0], acc[r][1], acc[r][2], acc[r][3]);
#pragma unroll
    for (int c = 0; c < 4; c++) {
        uint2 v;
        v.x = packh2(acc[0][c], acc[1][c]);
        v.y = packh2(acc[2][c], acc[3][c]);
        *reinterpret_cast<uint2*>(g_WhT + (size_t)(cb + c) * NN + i0 + rb) = v;
    }
    {
        float4 asv = *reinterpret_cast<const float4*>(a_vec + cb);
        float4 adv = *reinterpret_cast<const float4*>(a_vec + FOUT + cb);
#pragma unroll
        for (int r = 0; r < 4; r++) {
            float ss = acc[r][0] * asv.x + acc[r][1] * asv.y
                     + acc[r][2] * asv.z + acc[r][3] * asv.w;
            float sd = acc[r][0] * adv.x + acc[r][1] * adv.y
                     + acc[r][2] * adv.z + acc[r][3] * adv.w;
#pragma unroll
            for (int o = 16; o > 0; o >>= 1) {
                ss += __shfl_xor_sync(0xffffffffu, ss, o);
                sd += __shfl_xor_sync(0xffffffffu, sd, o);
            }
            if (lane == 0) {
                g_ss[i0 + rb + r] = ss;
                g_sd[i0 + rb + r] = sd;
            }
        }
    }
}

// ------- Phase 2: prescaled exp factors + counter reset -------
__global__ void __launch_bounds__(256) k_prep() {
    __shared__ float sm[8];
    __shared__ float sM;
    const int t = threadIdx.x;
    float m = -1e30f;
    for (int i = t; i < NN; i += 256) m = fmaxf(m, g_sd[i]);
#pragma unroll
    for (int o = 16; o > 0; o >>= 1) m = fmaxf(m, __shfl_xor_sync(0xffffffffu, m, o));
    if ((t & 31) == 0) sm[t >> 5] = m;
    __syncthreads();
    if (t == 0) {
        float r = sm[0];
#pragma unroll
        for (int i = 1; i < 8; i++) r = fmaxf(r, sm[i]);
        sM = r;
    }
    __syncthreads();
    const float M = sM;
    int i = blockIdx.x * 256 + t;
    if (blockIdx.x == 0 && t < NN / MT) g_cnt[t] = 0;   // reset combine counters
    float ss = g_ss[i], sd = g_sd[i];
    float x = ss + M;
    float LRm = x > 0.f ? x : 0.2f * x;
    g_us[i] = expf(ss - LRm);
    g_u5[i] = expf(fmaf(0.2f, ss, -LRm));
    g_vd[i] = expf(sd);
    g_v5[i] = expf(0.2f * sd);
}

// ------- Phase 3: fused numerator + in-kernel combine -------
extern __shared__ float dynsmem[];

__global__ void __launch_bounds__(256, 2) k_gat(const int* __restrict__ adj,
                                                float* __restrict__ out) {
    char* base = reinterpret_cast<char*>(dynsmem);
    const uint32_t sAu  = (uint32_t)__cvta_generic_to_shared(base);
    const uint32_t sBu0 = sAu + SA_BYTES;
    float* sDen = reinterpret_cast<float*>(base + SA_BYTES + 2 * SB_BYTES);

    const int t    = threadIdx.x;
    const int lane = t & 31;
    const int w    = t >> 5;
    const int ib    = blockIdx.x >> 1;
    const int i0    = ib * MT;
    const int halfj = blockIdx.x & 1;
    const int jbase = halfj * (NN / 2);
    const int jl    = lane * 4;

    float ssr[8], usr[8], u5r[8], den[8];
#pragma unroll
    for (int it = 0; it < 8; it++) {
        int gr = i0 + w + 8 * it;
        ssr[it] = g_ss[gr]; usr[it] = g_us[gr]; u5r[it] = g_u5[gr];
        den[it] = 0.f;
    }

    const int mrow = (w & 1) * 32;
    const int ncol = (w >> 1) * 32;
    const int qr   = lane >> 2;
    const int qc   = lane & 3;

    const int lr8 = lane & 7;
    const int lhb = (lane >> 3) & 1;
    const int lcb = lane >> 4;
    uint32_t aAdr[2], bAdr[2];
#pragma unroll
    for (int mb = 0; mb < 2; mb++) {
        int r = mrow + mb * 16 + lr8 + 8 * lhb;
        aAdr[mb] = sAu + (uint32_t)(r * SPH * 2) + (uint32_t)(lcb * 16);
    }
#pragma unroll
    for (int g = 0; g < 2; g++) {
        int r = ncol + g * 16 + lr8 + 8 * lhb;
        bAdr[g] = (uint32_t)(r * SBH * 2) + (uint32_t)(lcb * 16);
    }

    float acc[2][4][4];
#pragma unroll
    for (int mb = 0; mb < 2; mb++)
#pragma unroll
        for (int nb = 0; nb < 4; nb++)
#pragma unroll
            for (int c = 0; c < 4; c++) acc[mb][nb][c] = 0.f;

    // ---- prologue: B(0) cp.async + tile-0 regs ----
#pragma unroll
    for (int i = 0; i < 8; i++) {
        int g = t + 256 * i, n = g >> 4, c = g & 15;
        CPASYNC16(sBu0 + (uint32_t)(n * SBH * 2 + c * 16),
                  g_WhT + (size_t)n * NN + jbase + c * 8);
    }
    CPCOMMIT();
    float4 sdC = *reinterpret_cast<const float4*>(g_sd + jbase + jl);
    float4 vdC = *reinterpret_cast<const float4*>(g_vd + jbase + jl);
    float4 v5C = *reinterpret_cast<const float4*>(g_v5 + jbase + jl);
    unsigned mcur = 0;
#pragma unroll
    for (int it = 0; it < 8; it++) {
        int4 am = *reinterpret_cast<const int4*>(adj + (size_t)(i0 + w + 8 * it) * NN + jbase + jl);
        unsigned b = (am.x > 0 ? 1u : 0u) | (am.y > 0 ? 2u : 0u)
                   | (am.z > 0 ? 4u : 0u) | (am.w > 0 ? 8u : 0u);
        mcur |= b << (4 * it);
    }

    for (int jt = 0; jt < NT2; jt++) {
        const int s = jt & 1;

        // ---- P-gen(jt) -> sA (fp16) ----
#pragma unroll
        for (int it = 0; it < 8; it++) {
            int r = w + 8 * it;
            unsigned mk = mcur >> (4 * it);
            float p0 = (ssr[it] + sdC.x) > 0.f ? usr[it] * vdC.x : u5r[it] * v5C.x;
            float p1 = (ssr[it] + sdC.y) > 0.f ? usr[it] * vdC.y : u5r[it] * v5C.y;
            float p2 = (ssr[it] + sdC.z) > 0.f ? usr[it] * vdC.z : u5r[it] * v5C.z;
            float p3 = (ssr[it] + sdC.w) > 0.f ? usr[it] * vdC.w : u5r[it] * v5C.w;
            p0 = (mk & 1u) ? p0 : 0.f;
            p1 = (mk & 2u) ? p1 : 0.f;
            p2 = (mk & 4u) ? p2 : 0.f;
            p3 = (mk & 8u) ? p3 : 0.f;
            den[it] += (p0 + p1) + (p2 + p3);
            STS64(sAu + (uint32_t)(r * SPH + jl) * 2u, packh2(p0, p1), packh2(p2, p3));
        }

        // ---- prefetch regs(jt+1) ----
        if (jt + 1 < NT2) {
            const int j0n = jbase + (jt + 1) * JT;
            sdC = *reinterpret_cast<const float4*>(g_sd + j0n + jl);
            vdC = *reinterpret_cast<const float4*>(g_vd + j0n + jl);
            v5C = *reinterpret_cast<const float4*>(g_v5 + j0n + jl);
            unsigned mn = 0;
#pragma unroll
            for (int it = 0; it < 8; it++) {
                int4 am = *reinterpret_cast<const int4*>(
                    adj + (size_t)(i0 + w + 8 * it) * NN + j0n + jl);
                unsigned b = (am.x > 0 ? 1u : 0u) | (am.y > 0 ? 2u : 0u)
                           | (am.z > 0 ? 4u : 0u) | (am.w > 0 ? 8u : 0u);
                mn |= b << (4 * it);
            }
            mcur = mn;
        }

        // ---- cp.async B(jt+1) -> other buffer ----
        if (jt + 1 < NT2) {
            const __half* bsrc = g_WhT + jbase + (jt + 1) * JT;
            const uint32_t d = sBu0 + (uint32_t)(s ^ 1) * SB_BYTES;
#pragma unroll
            for (int i = 0; i < 8; i++) {
                int g = t + 256 * i, n = g >> 4, c = g & 15;
                CPASYNC16(d + (uint32_t)(n * SBH * 2 + c * 16),
                          bsrc + (size_t)n * NN + c * 8);
            }
        }
        CPCOMMIT();
        CPWAIT1();         // B(jt) resident
        __syncthreads();   // sA(jt) published

        // ---- MMA(jt): ldmatrix operands ----
        const uint32_t bS = sBu0 + (uint32_t)s * SB_BYTES;
#pragma unroll
        for (int ks = 0; ks < 8; ks++) {
            const uint32_t ko = (uint32_t)(ks * 32);
            unsigned a[2][4], b[2][4];
#pragma unroll
            for (int mb = 0; mb < 2; mb++)
                LDSM4(a[mb][0], a[mb][1], a[mb][2], a[mb][3], aAdr[mb] + ko);
#pragma unroll
            for (int g = 0; g < 2; g++)
                LDSM4(b[g][0], b[g][1], b[g][2], b[g][3], bS + bAdr[g] + ko);
#pragma unroll
            for (int mb = 0; mb < 2; mb++)
#pragma unroll
                for (int g = 0; g < 2; g++) {
                    MMA16(acc[mb][2 * g],     a[mb][0], a[mb][1], a[mb][2], a[mb][3],
                          b[g][0], b[g][2]);
                    MMA16(acc[mb][2 * g + 1], a[mb][0], a[mb][1], a[mb][2], a[mb][3],
                          b[g][1], b[g][3]);
                }
        }
        __syncthreads();   // sA / sB[s] free
    }

    // ---- partial denominators ----
#pragma unroll
    for (int it = 0; it < 8; it++) {
        float d = den[it];
#pragma unroll
        for (int o = 16; o > 0; o >>= 1) d += __shfl_xor_sync(0xffffffffu, d, o);
        if (lane == 0) sDen[w + 8 * it] = d;
    }
    __syncthreads();

    if (t < MT) g_pden[(size_t)halfj * NN + i0 + t] = sDen[t];
    float* pn = g_pnum + (size_t)halfj * NN * FOUT;
#pragma unroll
    for (int mb = 0; mb < 2; mb++) {
        const int rbase = mrow + mb * 16 + qr;
        const int r0 = i0 + rbase;
#pragma unroll
        for (int nb = 0; nb < 4; nb++) {
            int col = ncol + nb * 8 + qc * 2;
            *reinterpret_cast<float2*>(pn + (size_t)r0 * FOUT + col) =
                make_float2(acc[mb][nb][0], acc[mb][nb][1]);
            *reinterpret_cast<float2*>(pn + (size_t)(r0 + 8) * FOUT + col) =
                make_float2(acc[mb][nb][2], acc[mb][nb][3]);
        }
    }

    // ---- last-CTA-combines: second CTA of this row-block writes final out ----
    __threadfence();
    __shared__ int sOld;
    __syncthreads();
    if (t == 0) sOld = atomicAdd(&g_cnt[ib], 1);
    __syncthreads();
    if (sOld == 1) {
        const float* pn0 = g_pnum;
        const float* pn1 = g_pnum + (size_t)NN * FOUT;
#pragma unroll
        for (int i = 0; i < 8; i++) {
            int idx = t + 256 * i;                 // 2048 float4 = 64x128
            int row = idx >> 5;
            size_t off = (size_t)(i0 + row) * (FOUT / 4) + (idx & 31);
            float4 a = reinterpret_cast<const float4*>(pn0)[off];
            float4 b = reinterpret_cast<const float4*>(pn1)[off];
            float rd = 1.f / (g_pden[i0 + row] + g_pden[NN + i0 + row]);
            reinterpret_cast<float4*>(out)[off] = make_float4(
                (a.x + b.x) * rd, (a.y + b.y) * rd, (a.z + b.z) * rd, (a.w + b.w) * rd);
        }
    }
}

// ---------------------------------------------------------------
extern "C" void kernel_launch(void* const* d_in, const int* in_sizes, int n_in,
                              void* d_out, int out_size) {
    const float* h   = (const float*)d_in[0];
    const int*   adj = (const int*)d_in[1];
    const float* W   = (const float*)d_in[2];
    const float* a   = (const float*)d_in[3];
    float*       out = (float*)d_out;
    (void)in_sizes; (void)n_in; (void)out_size;

    const int smem_bytes = (int)(SA_BYTES + 2 * SB_BYTES) + 256;
    static int inited = 0;
    if (!inited) {
        cudaFuncSetAttribute(k_gat, cudaFuncAttributeMaxDynamicSharedMemorySize, smem_bytes);
        inited = 1;
    }
    k_wh<<<NN / 32, 256>>>(h, W, a);
    k_prep<<<NN / 256, 256>>>();
    k_gat<<<2 * (NN / MT), 256, smem_bytes>>>(adj, out);
}

// round 17
// speedup vs baseline: 1.2784x; 1.1383x over previous
#include <cuda_runtime.h>
#include <cuda_fp16.h>
#include <cstdint>
#include <cstddef>

#define NN   8192
#define FIN  256
#define FOUT 128
#define MT   64
#define JT   128
#define NT2  32
#define SPH  136
#define SBH  136
#define SA_BYTES 17408u
#define SB_BYTES 34816u
#define WROW 528u            // k_wh staging row stride bytes (264 halves)

__device__ __half g_WhT[FOUT * NN];
__device__ float  g_ss[NN], g_sd[NN];
__device__ float  g_us[NN], g_u5[NN];
__device__ float  g_vd[NN], g_v5[NN];
__device__ float  g_pnum[2 * NN * FOUT];
__device__ float  g_pden[2 * NN];
__device__ int    g_cnt[NN / MT];

#define CPASYNC16(dst, src) \
    asm volatile("cp.async.cg.shared.global [%0], [%1], 16;" :: "r"(dst), "l"(src))
#define CPCOMMIT() asm volatile("cp.async.commit_group;" ::: "memory")
#define CPWAIT1()  asm volatile("cp.async.wait_group 1;" ::: "memory")
#define STS32(a, x) \
    asm volatile("st.shared.b32 [%0], %1;" :: "r"(a), "r"(x) : "memory")
#define STS64(a, x, y) \
    asm volatile("st.shared.v2.b32 [%0], {%1,%2};" :: "r"(a), "r"(x), "r"(y) : "memory")
#define LDS64(v, a) \
    asm volatile("ld.shared.v2.b32 {%0,%1}, [%2];" : "=r"((v).x), "=r"((v).y) : "r"(a))
#define LDSM4(r0, r1, r2, r3, addr) \
    asm volatile("ldmatrix.sync.aligned.m8n8.x4.shared.b16 {%0,%1,%2,%3}, [%4];" \
                 : "=r"(r0), "=r"(r1), "=r"(r2), "=r"(r3) : "r"(addr))
#define MMA16(d, a0, a1, a2, a3, b0, b1) \
    asm volatile("mma.sync.aligned.m16n8k16.row.col.f32.f16.f16.f32 " \
                 "{%0,%1,%2,%3}, {%4,%5,%6,%7}, {%8,%9}, {%0,%1,%2,%3};\n" \
                 : "+f"(d[0]), "+f"(d[1]), "+f"(d[2]), "+f"(d[3]) \
                 : "r"(a0), "r"(a1), "r"(a2), "r"(a3), "r"(b0), "r"(b1))

__device__ __forceinline__ unsigned packh2(float a, float b) {
    __half2 h = __floats2half2_rn(a, b);
    return *reinterpret_cast<unsigned*>(&h);
}

extern __shared__ float dynsmem[];

// ------- Phase 1: Wh = h @ W^T via fp16 MMA; writes g_WhT + scores -------
__global__ void __launch_bounds__(256, 1) k_wh(const float* __restrict__ h,
                                               const float* __restrict__ W,
                                               const float* __restrict__ a_vec) {
    char* base = reinterpret_cast<char*>(dynsmem);
    const uint32_t sAu = (uint32_t)__cvta_generic_to_shared(base);
    const uint32_t sBu = sAu + 33792u;          // A: 64*528; B: 128*528

    const int t = threadIdx.x;
    const int lane = t & 31;
    const int w = t >> 5;
    const int i0 = blockIdx.x * 64;

    // ---- stage A (h tile, fp32 -> fp16) ----
#pragma unroll
    for (int i = 0; i < 16; i++) {
        int f4 = t + 256 * i, row = f4 >> 6, c4 = f4 & 63;
        float4 v = *reinterpret_cast<const float4*>(h + (size_t)(i0 + row) * FIN + c4 * 4);
        STS64(sAu + (uint32_t)(row * WROW + c4 * 8), packh2(v.x, v.y), packh2(v.z, v.w));
    }
    // ---- stage B (full W, fp32 -> fp16) ----
#pragma unroll
    for (int i = 0; i < 32; i++) {
        int f4 = t + 256 * i, n = f4 >> 6, c4 = f4 & 63;
        float4 v = *reinterpret_cast<const float4*>(W + (size_t)n * FIN + c4 * 4);
        STS64(sBu + (uint32_t)(n * WROW + c4 * 8), packh2(v.x, v.y), packh2(v.z, v.w));
    }
    __syncthreads();

    const int mrow = (w & 1) * 32;
    const int ncol = (w >> 1) * 32;
    const int qr = lane >> 2, qc = lane & 3;
    const int lr8 = lane & 7, lhb = (lane >> 3) & 1, lcb = lane >> 4;
    uint32_t aAdr[2], bAdr[2];
#pragma unroll
    for (int mb = 0; mb < 2; mb++)
        aAdr[mb] = sAu + (uint32_t)((mrow + mb * 16 + lr8 + 8 * lhb) * WROW) + (uint32_t)(lcb * 16);
#pragma unroll
    for (int g = 0; g < 2; g++)
        bAdr[g] = sBu + (uint32_t)((ncol + g * 16 + lr8 + 8 * lhb) * WROW) + (uint32_t)(lcb * 16);

    float acc[2][4][4];
#pragma unroll
    for (int mb = 0; mb < 2; mb++)
#pragma unroll
        for (int nb = 0; nb < 4; nb++)
#pragma unroll
            for (int c = 0; c < 4; c++) acc[mb][nb][c] = 0.f;

#pragma unroll
    for (int ks = 0; ks < 16; ks++) {
        const uint32_t ko = (uint32_t)(ks * 32);
        unsigned a[2][4], b[2][4];
#pragma unroll
        for (int mb = 0; mb < 2; mb++)
            LDSM4(a[mb][0], a[mb][1], a[mb][2], a[mb][3], aAdr[mb] + ko);
#pragma unroll
        for (int g = 0; g < 2; g++)
            LDSM4(b[g][0], b[g][1], b[g][2], b[g][3], bAdr[g] + ko);
#pragma unroll
        for (int mb = 0; mb < 2; mb++)
#pragma unroll
            for (int g = 0; g < 2; g++) {
                MMA16(acc[mb][2 * g],     a[mb][0], a[mb][1], a[mb][2], a[mb][3],
                      b[g][0], b[g][2]);
                MMA16(acc[mb][2 * g + 1], a[mb][0], a[mb][1], a[mb][2], a[mb][3],
                      b[g][1], b[g][3]);
            }
    }
    __syncthreads();

    // ---- fragments -> smem fp16 tile [64 rows][136-half stride] ----
#pragma unroll
    for (int mb = 0; mb < 2; mb++)
#pragma unroll
        for (int nb = 0; nb < 4; nb++) {
            int r0 = mrow + mb * 16 + qr, c = ncol + nb * 8 + qc * 2;
            STS32(sAu + (uint32_t)(r0 * 272 + c * 2),
                  packh2(acc[mb][nb][0], acc[mb][nb][1]));
            STS32(sAu + (uint32_t)((r0 + 8) * 272 + c * 2),
                  packh2(acc[mb][nb][2], acc[mb][nb][3]));
        }
    __syncthreads();

    // ---- coalesced transposed write: g_WhT[n][i0..i0+63] ----
#pragma unroll
    for (int i = 0; i < 4; i++) {
        int task = t + 256 * i, n = task >> 3, rg = task & 7;
        unsigned pk[4];
#pragma unroll
        for (int p = 0; p < 4; p++) {
            unsigned short lo, hi;
            asm("ld.shared.u16 %0, [%1];" : "=h"(lo)
                : "r"(sAu + (uint32_t)((rg * 8 + 2 * p) * 272 + n * 2)));
            asm("ld.shared.u16 %0, [%1];" : "=h"(hi)
                : "r"(sAu + (uint32_t)((rg * 8 + 2 * p + 1) * 272 + n * 2)));
            pk[p] = (unsigned)lo | ((unsigned)hi << 16);
        }
        *reinterpret_cast<uint4*>(g_WhT + (size_t)n * NN + i0 + rg * 8) =
            make_uint4(pk[0], pk[1], pk[2], pk[3]);
    }

    // ---- scores: warp w handles rows w*8 .. w*8+7 ----
    {
        float4 asv = *reinterpret_cast<const float4*>(a_vec + lane * 4);
        float4 adv = *reinterpret_cast<const float4*>(a_vec + FOUT + lane * 4);
#pragma unroll
        for (int r = 0; r < 8; r++) {
            int row = w * 8 + r;
            uint2 hv;
            LDS64(hv, sAu + (uint32_t)(row * 272 + lane * 8));
            float2 f01 = __half22float2(*reinterpret_cast<__half2*>(&hv.x));
            float2 f23 = __half22float2(*reinterpret_cast<__half2*>(&hv.y));
            float ss = f01.x * asv.x + f01.y * asv.y + f23.x * asv.z + f23.y * asv.w;
            float sd = f01.x * adv.x + f01.y * adv.y + f23.x * adv.z + f23.y * adv.w;
#pragma unroll
            for (int o = 16; o > 0; o >>= 1) {
                ss += __shfl_xor_sync(0xffffffffu, ss, o);
                sd += __shfl_xor_sync(0xffffffffu, sd, o);
            }
            if (lane == 0) { g_ss[i0 + row] = ss; g_sd[i0 + row] = sd; }
        }
    }
}

// ------- Phase 2: prescaled exp factors + counter reset -------
__global__ void __launch_bounds__(256) k_prep() {
    __shared__ float sm[8];
    __shared__ float sM;
    const int t = threadIdx.x;
    float m = -1e30f;
    for (int i = t; i < NN; i += 256) m = fmaxf(m, g_sd[i]);
#pragma unroll
    for (int o = 16; o > 0; o >>= 1) m = fmaxf(m, __shfl_xor_sync(0xffffffffu, m, o));
    if ((t & 31) == 0) sm[t >> 5] = m;
    __syncthreads();
    if (t == 0) {
        float r = sm[0];
#pragma unroll
        for (int i = 1; i < 8; i++) r = fmaxf(r, sm[i]);
        sM = r;
    }
    __syncthreads();
    const float M = sM;
    int i = blockIdx.x * 256 + t;
    if (blockIdx.x == 0 && t < NN / MT) g_cnt[t] = 0;
    float ss = g_ss[i], sd = g_sd[i];
    float x = ss + M;
    float LRm = x > 0.f ? x : 0.2f * x;
    g_us[i] = expf(ss - LRm);
    g_u5[i] = expf(fmaf(0.2f, ss, -LRm));
    g_vd[i] = expf(sd);
    g_v5[i] = expf(0.2f * sd);
}

// ------- Phase 3: fused numerator + in-kernel combine (R16 winner, unchanged) -------
__global__ void __launch_bounds__(256, 2) k_gat(const int* __restrict__ adj,
                                                float* __restrict__ out) {
    char* base = reinterpret_cast<char*>(dynsmem);
    const uint32_t sAu  = (uint32_t)__cvta_generic_to_shared(base);
    const uint32_t sBu0 = sAu + SA_BYTES;
    float* sDen = reinterpret_cast<float*>(base + SA_BYTES + 2 * SB_BYTES);

    const int t    = threadIdx.x;
    const int lane = t & 31;
    const int w    = t >> 5;
    const int ib    = blockIdx.x >> 1;
    const int i0    = ib * MT;
    const int halfj = blockIdx.x & 1;
    const int jbase = halfj * (NN / 2);
    const int jl    = lane * 4;

    float ssr[8], usr[8], u5r[8], den[8];
#pragma unroll
    for (int it = 0; it < 8; it++) {
        int gr = i0 + w + 8 * it;
        ssr[it] = g_ss[gr]; usr[it] = g_us[gr]; u5r[it] = g_u5[gr];
        den[it] = 0.f;
    }

    const int mrow = (w & 1) * 32;
    const int ncol = (w >> 1) * 32;
    const int qr   = lane >> 2;
    const int qc   = lane & 3;

    const int lr8 = lane & 7;
    const int lhb = (lane >> 3) & 1;
    const int lcb = lane >> 4;
    uint32_t aAdr[2], bAdr[2];
#pragma unroll
    for (int mb = 0; mb < 2; mb++) {
        int r = mrow + mb * 16 + lr8 + 8 * lhb;
        aAdr[mb] = sAu + (uint32_t)(r * SPH * 2) + (uint32_t)(lcb * 16);
    }
#pragma unroll
    for (int g = 0; g < 2; g++) {
        int r = ncol + g * 16 + lr8 + 8 * lhb;
        bAdr[g] = (uint32_t)(r * SBH * 2) + (uint32_t)(lcb * 16);
    }

    float acc[2][4][4];
#pragma unroll
    for (int mb = 0; mb < 2; mb++)
#pragma unroll
        for (int nb = 0; nb < 4; nb++)
#pragma unroll
            for (int c = 0; c < 4; c++) acc[mb][nb][c] = 0.f;

#pragma unroll
    for (int i = 0; i < 8; i++) {
        int g = t + 256 * i, n = g >> 4, c = g & 15;
        CPASYNC16(sBu0 + (uint32_t)(n * SBH * 2 + c * 16),
                  g_WhT + (size_t)n * NN + jbase + c * 8);
    }
    CPCOMMIT();
    float4 sdC = *reinterpret_cast<const float4*>(g_sd + jbase + jl);
    float4 vdC = *reinterpret_cast<const float4*>(g_vd + jbase + jl);
    float4 v5C = *reinterpret_cast<const float4*>(g_v5 + jbase + jl);
    unsigned mcur = 0;
#pragma unroll
    for (int it = 0; it < 8; it++) {
        int4 am = *reinterpret_cast<const int4*>(adj + (size_t)(i0 + w + 8 * it) * NN + jbase + jl);
        unsigned b = (am.x > 0 ? 1u : 0u) | (am.y > 0 ? 2u : 0u)
                   | (am.z > 0 ? 4u : 0u) | (am.w > 0 ? 8u : 0u);
        mcur |= b << (4 * it);
    }

    for (int jt = 0; jt < NT2; jt++) {
        const int s = jt & 1;

#pragma unroll
        for (int it = 0; it < 8; it++) {
            int r = w + 8 * it;
            unsigned mk = mcur >> (4 * it);
            float p0 = (ssr[it] + sdC.x) > 0.f ? usr[it] * vdC.x : u5r[it] * v5C.x;
            float p1 = (ssr[it] + sdC.y) > 0.f ? usr[it] * vdC.y : u5r[it] * v5C.y;
            float p2 = (ssr[it] + sdC.z) > 0.f ? usr[it] * vdC.z : u5r[it] * v5C.z;
            float p3 = (ssr[it] + sdC.w) > 0.f ? usr[it] * vdC.w : u5r[it] * v5C.w;
            p0 = (mk & 1u) ? p0 : 0.f;
            p1 = (mk & 2u) ? p1 : 0.f;
            p2 = (mk & 4u) ? p2 : 0.f;
            p3 = (mk & 8u) ? p3 : 0.f;
            den[it] += (p0 + p1) + (p2 + p3);
            STS64(sAu + (uint32_t)(r * SPH + jl) * 2u, packh2(p0, p1), packh2(p2, p3));
        }

        if (jt + 1 < NT2) {
            const int j0n = jbase + (jt + 1) * JT;
            sdC = *reinterpret_cast<const float4*>(g_sd + j0n + jl);
            vdC = *reinterpret_cast<const float4*>(g_vd + j0n + jl);
            v5C = *reinterpret_cast<const float4*>(g_v5 + j0n + jl);
            unsigned mn = 0;
#pragma unroll
            for (int it = 0; it < 8; it++) {
                int4 am = *reinterpret_cast<const int4*>(
                    adj + (size_t)(i0 + w + 8 * it) * NN + j0n + jl);
                unsigned b = (am.x > 0 ? 1u : 0u) | (am.y > 0 ? 2u : 0u)
                           | (am.z > 0 ? 4u : 0u) | (am.w > 0 ? 8u : 0u);
                mn |= b << (4 * it);
            }
            mcur = mn;
        }

        if (jt + 1 < NT2) {
            const __half* bsrc = g_WhT + jbase + (jt + 1) * JT;
            const uint32_t d = sBu0 + (uint32_t)(s ^ 1) * SB_BYTES;
#pragma unroll
            for (int i = 0; i < 8; i++) {
                int g = t + 256 * i, n = g >> 4, c = g & 15;
                CPASYNC16(d + (uint32_t)(n * SBH * 2 + c * 16),
                          bsrc + (size_t)n * NN + c * 8);
            }
        }
        CPCOMMIT();
        CPWAIT1();
        __syncthreads();

        const uint32_t bS = sBu0 + (uint32_t)s * SB_BYTES;
#pragma unroll
        for (int ks = 0; ks < 8; ks++) {
            const uint32_t ko = (uint32_t)(ks * 32);
            unsigned a[2][4], b[2][4];
#pragma unroll
            for (int mb = 0; mb < 2; mb++)
                LDSM4(a[mb][0], a[mb][1], a[mb][2], a[mb][3], aAdr[mb] + ko);
#pragma unroll
            for (int g = 0; g < 2; g++)
                LDSM4(b[g][0], b[g][1], b[g][2], b[g][3], bS + bAdr[g] + ko);
#pragma unroll
            for (int mb = 0; mb < 2; mb++)
#pragma unroll
                for (int g = 0; g < 2; g++) {
                    MMA16(acc[mb][2 * g],     a[mb][0], a[mb][1], a[mb][2], a[mb][3],
                          b[g][0], b[g][2]);
                    MMA16(acc[mb][2 * g + 1], a[mb][0], a[mb][1], a[mb][2], a[mb][3],
                          b[g][1], b[g][3]);
                }
        }
        __syncthreads();
    }

#pragma unroll
    for (int it = 0; it < 8; it++) {
        float d = den[it];
#pragma unroll
        for (int o = 16; o > 0; o >>= 1) d += __shfl_xor_sync(0xffffffffu, d, o);
        if (lane == 0) sDen[w + 8 * it] = d;
    }
    __syncthreads();

    if (t < MT) g_pden[(size_t)halfj * NN + i0 + t] = sDen[t];
    float* pn = g_pnum + (size_t)halfj * NN * FOUT;
#pragma unroll
    for (int mb = 0; mb < 2; mb++) {
        const int rbase = mrow + mb * 16 + qr;
        const int r0 = i0 + rbase;
#pragma unroll
        for (int nb = 0; nb < 4; nb++) {
            int col = ncol + nb * 8 + qc * 2;
            *reinterpret_cast<float2*>(pn + (size_t)r0 * FOUT + col) =
                make_float2(acc[mb][nb][0], acc[mb][nb][1]);
            *reinterpret_cast<float2*>(pn + (size_t)(r0 + 8) * FOUT + col) =
                make_float2(acc[mb][nb][2], acc[mb][nb][3]);
        }
    }

    __threadfence();
    __shared__ int sOld;
    __syncthreads();
    if (t == 0) sOld = atomicAdd(&g_cnt[ib], 1);
    __syncthreads();
    if (sOld == 1) {
        const float* pn0 = g_pnum;
        const float* pn1 = g_pnum + (size_t)NN * FOUT;
#pragma unroll
        for (int i = 0; i < 8; i++) {
            int idx = t + 256 * i;
            int row = idx >> 5;
            size_t off = (size_t)(i0 + row) * (FOUT / 4) + (idx & 31);
            float4 a = reinterpret_cast<const float4*>(pn0)[off];
            float4 b = reinterpret_cast<const float4*>(pn1)[off];
            float rd = 1.f / (g_pden[i0 + row] + g_pden[NN + i0 + row]);
            reinterpret_cast<float4*>(out)[off] = make_float4(
                (a.x + b.x) * rd, (a.y + b.y) * rd, (a.z + b.z) * rd, (a.w + b.w) * rd);
        }
    }
}

// ---------------------------------------------------------------
extern "C" void kernel_launch(void* const* d_in, const int* in_sizes, int n_in,
                              void* d_out, int out_size) {
    const float* h   = (const float*)d_in[0];
    const int*   adj = (const int*)d_in[1];
    const float* W   = (const float*)d_in[2];
    const float* a   = (const float*)d_in[3];
    float*       out = (float*)d_out;
    (void)in_sizes; (void)n_in; (void)out_size;

    const int smem_gat = (int)(SA_BYTES + 2 * SB_BYTES) + 256;
    const int smem_wh  = 33792 + 67584;          // 101376
    static int inited = 0;
    if (!inited) {
        cudaFuncSetAttribute(k_gat, cudaFuncAttributeMaxDynamicSharedMemorySize, smem_gat);
        cudaFuncSetAttribute(k_wh,  cudaFuncAttributeMaxDynamicSharedMemorySize, smem_wh);
        inited = 1;
    }
    k_wh<<<NN / 64, 256, smem_wh>>>(h, W, a);
    k_prep<<<NN / 256, 256>>>();
    k_gat<<<2 * (NN / MT), 256, smem_gat>>>(adj, out);
}